// round 1
// baseline (speedup 1.0000x reference)
#include <cuda_runtime.h>
#include <math_constants.h>

#define BB   32
#define NP   1024
#define KNN  20
#define NPTS (BB*NP)

// ---------------- scratch (device globals; no allocation allowed) ----------
__device__ float g_D[(size_t)BB*NP*NP];     // 128MB distance matrix (reused)
__device__ int   g_idx[NPTS*KNN];
__device__ float g_p1[NPTS*64];
__device__ float g_q1[NPTS*64];
__device__ float g_f1[NPTS*64];
__device__ float g_p2[NPTS*128];
__device__ float g_q2[NPTS*128];
__device__ float g_f2[NPTS*128];
__device__ float g_pool[BB*512];

// ---------------- 1) pairwise distances on xyz -----------------------------
__global__ void dist3_kernel(const float* __restrict__ x) {
    __shared__ float sx[NP], sy[NP], sz[NP], sq[NP];
    int b = blockIdx.x, tile = blockIdx.y;
    const float* xb = x + (size_t)b * NP * 3;
    for (int i = threadIdx.x; i < NP; i += blockDim.x) {
        float a0 = xb[i*3], a1 = xb[i*3+1], a2 = xb[i*3+2];
        sx[i] = a0; sy[i] = a1; sz[i] = a2;
        sq[i] = a0*a0 + a1*a1 + a2*a2;
    }
    __syncthreads();
    float* Db = g_D + (size_t)b * NP * NP;
    for (int r = 0; r < 128; r++) {
        int n = tile * 128 + r;
        float qx = sx[n], qy = sy[n], qz = sz[n], qs = sq[n];
        float* Dn = Db + (size_t)n * NP;
        for (int m = threadIdx.x; m < NP; m += blockDim.x) {
            float dot = qx*sx[m] + qy*sy[m] + qz*sz[m];
            float d = qs + sq[m] - 2.0f * dot;
            Dn[m] = (m == n) ? CUDART_INF_F : d;
        }
    }
}

// ---------------- 2) top-20 smallest per row (warp per row) ----------------
__global__ void topk_kernel() {
    int row  = blockIdx.x * 8 + (threadIdx.x >> 5);
    int lane = threadIdx.x & 31;
    const float* d = g_D + (size_t)row * NP;
    float v[32];
#pragma unroll
    for (int i = 0; i < 32; i++) v[i] = d[lane + (i << 5)];
    // cached local argmin (candidate global index = lane + 32*i)
    float bv = v[0]; int bi = 0;
#pragma unroll
    for (int i = 1; i < 32; i++) if (v[i] < bv) { bv = v[i]; bi = i; }

    for (int r = 0; r < KNN; r++) {
        float mv = bv;
        int   mi = (bi << 5) | lane;
#pragma unroll
        for (int off = 16; off > 0; off >>= 1) {
            float ov = __shfl_down_sync(0xffffffffu, mv, off);
            int   oi = __shfl_down_sync(0xffffffffu, mi, off);
            if (ov < mv || (ov == mv && oi < mi)) { mv = ov; mi = oi; }
        }
        mi = __shfl_sync(0xffffffffu, mi, 0);
        if (lane == 0) g_idx[row * KNN + r] = mi;
        if ((mi & 31) == lane) {          // winner lane pops + rescans
            int slot = mi >> 5;
#pragma unroll
            for (int i = 0; i < 32; i++) if (i == slot) v[i] = CUDART_INF_F;
            bv = v[0]; bi = 0;
#pragma unroll
            for (int i = 1; i < 32; i++) if (v[i] < bv) { bv = v[i]; bi = i; }
        }
    }
}

// ---------------- 3) EdgeConv1 layer-1 split precompute --------------------
// p1 = x@(W1a-W1b)+b1, q1 = x@W1b   (W1: [6,64], rows 0..2 = x_i, 3..5 = x_j-x_i)
__global__ void pre1_kernel(const float* __restrict__ x,
                            const float* __restrict__ W1,
                            const float* __restrict__ b1) {
    int id = blockIdx.x * blockDim.x + threadIdx.x;
    if (id >= NPTS * 64) return;
    int n = id >> 6, t = id & 63;
    float x0 = x[n*3], x1 = x[n*3+1], x2 = x[n*3+2];
    float wa0 = W1[t],       wa1 = W1[64 + t],  wa2 = W1[128 + t];
    float wb0 = W1[192 + t], wb1 = W1[256 + t], wb2 = W1[320 + t];
    float q = x0*wb0 + x1*wb1 + x2*wb2;
    float p = b1[t] + x0*(wa0-wb0) + x1*(wa1-wb1) + x2*(wa2-wb2);
    g_p1[id] = p;
    g_q1[id] = q;
}

// ---------------- 4) EdgeConv1 fused: relu(p+q) -> L2 -> L3 -> max over k --
// one thread per point; h in registers; e/h staged in a private padded SMEM row
#define EC1_SMEM ((4096 + 4096 + 64 + 64 + 64*65) * 4)
__global__ void __launch_bounds__(64) ec1_kernel(const float* __restrict__ W2,
                                                 const float* __restrict__ b2,
                                                 const float* __restrict__ W3,
                                                 const float* __restrict__ b3) {
    extern __shared__ float sm[];
    float* sW2 = sm;
    float* sW3 = sm + 4096;
    float* sB2 = sm + 8192;
    float* sB3 = sm + 8256;
    float* sE  = sm + 8320;
    int tid = threadIdx.x;
    for (int i = tid; i < 4096; i += 64) { sW2[i] = W2[i]; sW3[i] = W3[i]; }
    sB2[tid] = b2[tid];
    sB3[tid] = b3[tid];
    __syncthreads();

    int n = blockIdx.x * 64 + tid;
    int b = n >> 10;
    float* myE = sE + tid * 65;
    const float* pp   = g_p1 + (size_t)n * 64;
    const int*   idxp = g_idx + n * KNN;

    float best[64];
#pragma unroll
    for (int t = 0; t < 64; t++) best[t] = 0.0f;   // relu outputs are >=0

    for (int k = 0; k < KNN; k++) {
        int j = idxp[k];
        const float* qq = g_q1 + ((size_t)(b << 10) + j) * 64;
#pragma unroll
        for (int c = 0; c < 64; c += 4) {
            float4 pv = *(const float4*)(pp + c);
            float4 qv = *(const float4*)(qq + c);
            myE[c+0] = fmaxf(pv.x + qv.x, 0.0f);
            myE[c+1] = fmaxf(pv.y + qv.y, 0.0f);
            myE[c+2] = fmaxf(pv.z + qv.z, 0.0f);
            myE[c+3] = fmaxf(pv.w + qv.w, 0.0f);
        }
        float h[64];
#pragma unroll
        for (int t = 0; t < 64; t++) h[t] = sB2[t];
#pragma unroll 4
        for (int c = 0; c < 64; c++) {
            float ec = myE[c];
            const float4* w = (const float4*)(sW2 + (c << 6));
#pragma unroll
            for (int t = 0; t < 16; t++) {
                float4 wv = w[t];
                h[4*t+0] = fmaf(ec, wv.x, h[4*t+0]);
                h[4*t+1] = fmaf(ec, wv.y, h[4*t+1]);
                h[4*t+2] = fmaf(ec, wv.z, h[4*t+2]);
                h[4*t+3] = fmaf(ec, wv.w, h[4*t+3]);
            }
        }
#pragma unroll
        for (int t = 0; t < 64; t++) myE[t] = fmaxf(h[t], 0.0f);
#pragma unroll
        for (int t = 0; t < 64; t++) h[t] = sB3[t];
#pragma unroll 4
        for (int c = 0; c < 64; c++) {
            float ec = myE[c];
            const float4* w = (const float4*)(sW3 + (c << 6));
#pragma unroll
            for (int t = 0; t < 16; t++) {
                float4 wv = w[t];
                h[4*t+0] = fmaf(ec, wv.x, h[4*t+0]);
                h[4*t+1] = fmaf(ec, wv.y, h[4*t+1]);
                h[4*t+2] = fmaf(ec, wv.z, h[4*t+2]);
                h[4*t+3] = fmaf(ec, wv.w, h[4*t+3]);
            }
        }
#pragma unroll
        for (int t = 0; t < 64; t++) best[t] = fmaxf(best[t], h[t]); // best>=0 folds relu
    }
    float* out = g_f1 + (size_t)n * 64;
#pragma unroll
    for (int t = 0; t < 64; t++) out[t] = best[t];
}

// ---------------- 5) pairwise distances on 64-d features (tiled GEMM) ------
#define TS 132
__global__ void dist64_kernel() {
    __shared__ float sAt[32 * TS];   // [k][m], transposed tiles
    __shared__ float sBt[32 * TS];
    int b  = blockIdx.z;
    int m0 = blockIdx.y * 128, n0 = blockIdx.x * 128;
    int tid = threadIdx.x;
    int tx = tid & 15, ty = tid >> 4;
    const float* F = g_f1 + (size_t)b * NP * 64;

    float acc[8][8], na[8], nb[8];
#pragma unroll
    for (int i = 0; i < 8; i++) {
        na[i] = 0.0f; nb[i] = 0.0f;
#pragma unroll
        for (int j = 0; j < 8; j++) acc[i][j] = 0.0f;
    }
    for (int kc = 0; kc < 2; kc++) {
        __syncthreads();
#pragma unroll
        for (int l = 0; l < 16; l++) {
            int idx = l * 256 + tid;
            int r = idx >> 5, c = idx & 31;
            sAt[c * TS + r] = F[(size_t)(m0 + r) * 64 + kc * 32 + c];
            sBt[c * TS + r] = F[(size_t)(n0 + r) * 64 + kc * 32 + c];
        }
        __syncthreads();
        for (int k = 0; k < 32; k++) {
            float4 a0 = *(const float4*)(sAt + k * TS + ty * 8);
            float4 a1 = *(const float4*)(sAt + k * TS + ty * 8 + 4);
            float4 c0 = *(const float4*)(sBt + k * TS + tx * 8);
            float4 c1 = *(const float4*)(sBt + k * TS + tx * 8 + 4);
            float a[8]  = {a0.x, a0.y, a0.z, a0.w, a1.x, a1.y, a1.z, a1.w};
            float bv[8] = {c0.x, c0.y, c0.z, c0.w, c1.x, c1.y, c1.z, c1.w};
#pragma unroll
            for (int i = 0; i < 8; i++) na[i] = fmaf(a[i], a[i], na[i]);
#pragma unroll
            for (int j = 0; j < 8; j++) nb[j] = fmaf(bv[j], bv[j], nb[j]);
#pragma unroll
            for (int i = 0; i < 8; i++)
#pragma unroll
                for (int j = 0; j < 8; j++) acc[i][j] = fmaf(a[i], bv[j], acc[i][j]);
        }
    }
    float* Dp = g_D + (size_t)b * NP * NP;
#pragma unroll
    for (int i = 0; i < 8; i++) {
        int row = m0 + ty * 8 + i;
#pragma unroll
        for (int j = 0; j < 8; j++) {
            int col = n0 + tx * 8 + j;
            float d = na[i] + nb[j] - 2.0f * acc[i][j];
            Dp[(size_t)row * NP + col] = (row == col) ? CUDART_INF_F : d;
        }
    }
}

// ---------------- 6) EdgeConv2 layer split precompute -----------------------
// p2 = f1@(W4a-W4b)+b4, q2 = f1@W4b   (W4: [128,128], rows 0..63 / 64..127)
#define PRE2_SMEM ((8192 + 8192 + 4096) * 4)
__global__ void pre2_kernel(const float* __restrict__ W4,
                            const float* __restrict__ b4) {
    extern __shared__ float sm[];
    float* sWd = sm;              // W4a - W4b  [64][128]
    float* sWb = sm + 8192;       // W4b        [64][128]
    float* sF  = sm + 16384;      // f1 tile    [64][64]
    int tid = threadIdx.x;
    int base = blockIdx.x * 64;
    for (int i = tid; i < 8192; i += 256) {
        int c = i >> 7, t = i & 127;
        float wa = W4[c * 128 + t];
        float wb = W4[(64 + c) * 128 + t];
        sWd[i] = wa - wb;
        sWb[i] = wb;
    }
    for (int i = tid; i < 4096; i += 256) sF[i] = g_f1[(size_t)base * 64 + i];
    __syncthreads();

    int t = tid & 127;
    int half = tid >> 7;
    float bias = b4[t];
    for (int pp = 0; pp < 32; pp++) {
        int lp = (pp << 1) + half;
        const float* fr = sF + lp * 64;
        float accp = bias, accq = 0.0f;
#pragma unroll 8
        for (int c = 0; c < 64; c++) {
            float f = fr[c];
            accp = fmaf(f, sWd[c * 128 + t], accp);
            accq = fmaf(f, sWb[c * 128 + t], accq);
        }
        g_p2[(size_t)(base + lp) * 128 + t] = accp;
        g_q2[(size_t)(base + lp) * 128 + t] = accq;
    }
}

// ---------------- 7) EdgeConv2: max_k relu(p + q) ---------------------------
__global__ void ec2_kernel() {
    int n = blockIdx.x, t = threadIdx.x;
    int b = n >> 10;
    float p = g_p2[(size_t)n * 128 + t];
    const int* idxp = g_idx + n * KNN;
    float best = 0.0f;    // relu fold
#pragma unroll
    for (int k = 0; k < KNN; k++) {
        int j = idxp[k];
        float q = g_q2[((size_t)(b << 10) + j) * 128 + t];
        best = fmaxf(best, p + q);
    }
    g_f2[(size_t)n * 128 + t] = best;
}

// ---------------- 8) pool: relu(f2@Wp+bp), max over points -----------------
__global__ void zero_pool_kernel() {
    int i = blockIdx.x * blockDim.x + threadIdx.x;
    if (i < BB * 512) g_pool[i] = 0.0f;
}

__global__ void pool_kernel(const float* __restrict__ Wp,
                            const float* __restrict__ bp) {
    __shared__ float sAt[32 * TS];
    __shared__ float sBt[32 * TS];
    __shared__ float sred[16 * 128];
    int m0 = blockIdx.x * 128, n0 = blockIdx.y * 128;
    int b  = m0 >> 10;
    int tid = threadIdx.x;
    int tx = tid & 15, ty = tid >> 4;

    float acc[8][8];
#pragma unroll
    for (int i = 0; i < 8; i++)
#pragma unroll
        for (int j = 0; j < 8; j++) acc[i][j] = 0.0f;

    for (int kc = 0; kc < 4; kc++) {
        __syncthreads();
#pragma unroll
        for (int l = 0; l < 16; l++) {
            int idx = l * 256 + tid;
            int r = idx >> 5, c = idx & 31;
            sAt[c * TS + r] = g_f2[(size_t)(m0 + r) * 128 + kc * 32 + c];
        }
#pragma unroll
        for (int l = 0; l < 16; l++) {
            int idx = l * 256 + tid;
            int nl = idx & 127, kk = idx >> 7;
            sBt[kk * TS + nl] = Wp[(size_t)(kc * 32 + kk) * 512 + n0 + nl];
        }
        __syncthreads();
        for (int k = 0; k < 32; k++) {
            float4 a0 = *(const float4*)(sAt + k * TS + ty * 8);
            float4 a1 = *(const float4*)(sAt + k * TS + ty * 8 + 4);
            float4 c0 = *(const float4*)(sBt + k * TS + tx * 8);
            float4 c1 = *(const float4*)(sBt + k * TS + tx * 8 + 4);
            float a[8]  = {a0.x, a0.y, a0.z, a0.w, a1.x, a1.y, a1.z, a1.w};
            float bv[8] = {c0.x, c0.y, c0.z, c0.w, c1.x, c1.y, c1.z, c1.w};
#pragma unroll
            for (int i = 0; i < 8; i++)
#pragma unroll
                for (int j = 0; j < 8; j++) acc[i][j] = fmaf(a[i], bv[j], acc[i][j]);
        }
    }
    // relu + column max over this block's 128 rows, then atomic max
#pragma unroll
    for (int j = 0; j < 8; j++) {
        int col = n0 + tx * 8 + j;
        float bpv = bp[col];
        float cm = 0.0f;   // relu fold
#pragma unroll
        for (int i = 0; i < 8; i++) cm = fmaxf(cm, acc[i][j] + bpv);
        sred[ty * 128 + tx * 8 + j] = cm;
    }
    __syncthreads();
    if (ty == 0) {
#pragma unroll
        for (int j = 0; j < 8; j++) {
            float cm = 0.0f;
#pragma unroll
            for (int yy = 0; yy < 16; yy++) cm = fmaxf(cm, sred[yy * 128 + tx * 8 + j]);
            atomicMax((int*)&g_pool[b * 512 + n0 + tx * 8 + j], __float_as_int(cm));
        }
    }
}

// ---------------- 9) classifier head ----------------------------------------
__global__ void head_kernel(const float* __restrict__ Wt1, const float* __restrict__ bt1,
                            const float* __restrict__ Wt2, const float* __restrict__ bt2,
                            float* __restrict__ out) {
    __shared__ float sp[512];
    __shared__ float st[256];
    int b = blockIdx.x, t = threadIdx.x;
    sp[t]       = g_pool[b * 512 + t];
    sp[256 + t] = g_pool[b * 512 + 256 + t];
    __syncthreads();
    float acc = bt1[t];
#pragma unroll 8
    for (int c = 0; c < 512; c++) acc = fmaf(sp[c], Wt1[c * 256 + t], acc);
    st[t] = fmaxf(acc, 0.0f);
    __syncthreads();
    if (t < 40) {
        float a2 = bt2[t];
#pragma unroll 8
        for (int c = 0; c < 256; c++) a2 = fmaf(st[c], Wt2[c * 40 + t], a2);
        out[b * 40 + t] = a2;
    }
}

// ---------------- launch -----------------------------------------------------
extern "C" void kernel_launch(void* const* d_in, const int* in_sizes, int n_in,
                              void* d_out, int out_size) {
    const float* x   = (const float*)d_in[0];
    // d_in[1] = batch (int64) — layout is fixed B x N, unused
    const float* W1  = (const float*)d_in[2];
    const float* b1  = (const float*)d_in[3];
    const float* W2  = (const float*)d_in[4];
    const float* b2  = (const float*)d_in[5];
    const float* W3  = (const float*)d_in[6];
    const float* b3  = (const float*)d_in[7];
    const float* W4  = (const float*)d_in[8];
    const float* b4  = (const float*)d_in[9];
    const float* Wp  = (const float*)d_in[10];
    const float* bp  = (const float*)d_in[11];
    const float* Wt1 = (const float*)d_in[12];
    const float* bt1 = (const float*)d_in[13];
    const float* Wt2 = (const float*)d_in[14];
    const float* bt2 = (const float*)d_in[15];
    float* out = (float*)d_out;

    cudaFuncSetAttribute(ec1_kernel,  cudaFuncAttributeMaxDynamicSharedMemorySize, EC1_SMEM);
    cudaFuncSetAttribute(pre2_kernel, cudaFuncAttributeMaxDynamicSharedMemorySize, PRE2_SMEM);

    // Stage 1: kNN on xyz + EdgeConv1
    dist3_kernel<<<dim3(BB, 8), 256>>>(x);
    topk_kernel<<<NPTS / 8, 256>>>();
    pre1_kernel<<<(NPTS * 64) / 256, 256>>>(x, W1, b1);
    ec1_kernel<<<NPTS / 64, 64, EC1_SMEM>>>(W2, b2, W3, b3);

    // Stage 2: kNN on 64-d features + EdgeConv2 (layer-split, GEMM-free edges)
    dist64_kernel<<<dim3(8, 8, BB), 256>>>();
    topk_kernel<<<NPTS / 8, 256>>>();
    pre2_kernel<<<NPTS / 64, 256, PRE2_SMEM>>>(W4, b4);
    ec2_kernel<<<NPTS, 128>>>();

    // Stage 3: point MLP + global max pool + head
    zero_pool_kernel<<<16, 1024>>>();
    pool_kernel<<<dim3(256, 4), 256>>>(Wp, bp);
    head_kernel<<<BB, 256>>>(Wt1, bt1, Wt2, bt2, out);
}

// round 3
// speedup vs baseline: 1.2263x; 1.2263x over previous
#include <cuda_runtime.h>
#include <math_constants.h>

#define BB   32
#define NP   1024
#define KNN  20
#define NPTS (BB*NP)
#define NEDGE (NPTS*KNN)

// ---------------- scratch (device globals; no allocation allowed) ----------
__device__ float g_D[(size_t)BB*NP*NP];     // 128MB distance matrix (stage-2 only)
__device__ int   g_idx[NPTS*KNN];
__device__ float g_p1[NPTS*64];
__device__ float g_q1[NPTS*64];
__device__ float g_f1[NPTS*64];
__device__ float g_p2[NPTS*128];
__device__ float g_q2[NPTS*128];
__device__ float g_f2[NPTS*128];
__device__ float g_pool[BB*512];

// ---------------- 1) fused kNN on xyz: distances in regs + top-20 ----------
__global__ void __launch_bounds__(256) knn3_kernel(const float* __restrict__ x) {
    __shared__ float sx[NP], sy[NP], sz[NP], sq[NP];
    int rowBase = blockIdx.x * 8;          // 8 rows (one per warp), never straddles batch
    int b = rowBase >> 10;
    const float* xb = x + (size_t)b * NP * 3;
    for (int i = threadIdx.x; i < NP; i += 256) {
        float a0 = xb[i*3], a1 = xb[i*3+1], a2 = xb[i*3+2];
        sx[i] = a0; sy[i] = a1; sz[i] = a2;
        sq[i] = a0*a0 + a1*a1 + a2*a2;
    }
    __syncthreads();

    int warp = threadIdx.x >> 5;
    int lane = threadIdx.x & 31;
    int n  = rowBase + warp;               // global point id (for g_idx output)
    int nl = n & (NP - 1);                 // LOCAL row index within batch (for smem)
    float qx = sx[nl], qy = sy[nl], qz = sz[nl], qs = sq[nl];

    float v[32];
#pragma unroll
    for (int i = 0; i < 32; i++) {
        int m = lane + (i << 5);
        float dot = qx*sx[m] + qy*sy[m] + qz*sz[m];
        float d = qs + sq[m] - 2.0f * dot;
        v[i] = (m == nl) ? CUDART_INF_F : d;
    }
    float bv = v[0]; int bi = 0;
#pragma unroll
    for (int i = 1; i < 32; i++) if (v[i] < bv) { bv = v[i]; bi = i; }

    for (int r = 0; r < KNN; r++) {
        float mv = bv;
        int   mi = (bi << 5) | lane;
#pragma unroll
        for (int off = 16; off > 0; off >>= 1) {
            float ov = __shfl_down_sync(0xffffffffu, mv, off);
            int   oi = __shfl_down_sync(0xffffffffu, mi, off);
            if (ov < mv || (ov == mv && oi < mi)) { mv = ov; mi = oi; }
        }
        mi = __shfl_sync(0xffffffffu, mi, 0);
        if (lane == 0) g_idx[n * KNN + r] = mi;   // mi is batch-local neighbor id
        if ((mi & 31) == lane) {
            int slot = mi >> 5;
#pragma unroll
            for (int i = 0; i < 32; i++) if (i == slot) v[i] = CUDART_INF_F;
            bv = v[0]; bi = 0;
#pragma unroll
            for (int i = 1; i < 32; i++) if (v[i] < bv) { bv = v[i]; bi = i; }
        }
    }
}

// ---------------- 2) top-20 smallest per row of g_D (stage 2) --------------
__global__ void topk_kernel() {
    int row  = blockIdx.x * 8 + (threadIdx.x >> 5);
    int lane = threadIdx.x & 31;
    const float* d = g_D + (size_t)row * NP;
    float v[32];
#pragma unroll
    for (int i = 0; i < 32; i++) v[i] = d[lane + (i << 5)];
    float bv = v[0]; int bi = 0;
#pragma unroll
    for (int i = 1; i < 32; i++) if (v[i] < bv) { bv = v[i]; bi = i; }

    for (int r = 0; r < KNN; r++) {
        float mv = bv;
        int   mi = (bi << 5) | lane;
#pragma unroll
        for (int off = 16; off > 0; off >>= 1) {
            float ov = __shfl_down_sync(0xffffffffu, mv, off);
            int   oi = __shfl_down_sync(0xffffffffu, mi, off);
            if (ov < mv || (ov == mv && oi < mi)) { mv = ov; mi = oi; }
        }
        mi = __shfl_sync(0xffffffffu, mi, 0);
        if (lane == 0) g_idx[row * KNN + r] = mi;
        if ((mi & 31) == lane) {
            int slot = mi >> 5;
#pragma unroll
            for (int i = 0; i < 32; i++) if (i == slot) v[i] = CUDART_INF_F;
            bv = v[0]; bi = 0;
#pragma unroll
            for (int i = 1; i < 32; i++) if (v[i] < bv) { bv = v[i]; bi = i; }
        }
    }
}

// ---------------- 3) EdgeConv1 layer-1 split precompute (+ zero f1) --------
__global__ void pre1_kernel(const float* __restrict__ x,
                            const float* __restrict__ W1,
                            const float* __restrict__ b1) {
    int id = blockIdx.x * blockDim.x + threadIdx.x;
    if (id >= NPTS * 64) return;
    int n = id >> 6, t = id & 63;
    float x0 = x[n*3], x1 = x[n*3+1], x2 = x[n*3+2];
    float wa0 = W1[t],       wa1 = W1[64 + t],  wa2 = W1[128 + t];
    float wb0 = W1[192 + t], wb1 = W1[256 + t], wb2 = W1[320 + t];
    float q = x0*wb0 + x1*wb1 + x2*wb2;
    float p = b1[t] + x0*(wa0-wb0) + x1*(wa1-wb1) + x2*(wa2-wb2);
    g_p1[id] = p;
    g_q1[id] = q;
    g_f1[id] = 0.0f;   // for atomicMax epilogue of ec1
}

// ---------------- 4) EdgeConv1 fused 2-layer GEMM over 256-edge tiles ------
// smem: ET[64][260] (66560B) | W2[64][64] | W3[64][64] | b2 | b3
#define ETP 260
#define EC1_SMEM ((64*ETP + 4096 + 4096 + 64 + 64) * 4)
__global__ void __launch_bounds__(256, 2) ec1_kernel(const float* __restrict__ W2,
                                                     const float* __restrict__ b2,
                                                     const float* __restrict__ W3,
                                                     const float* __restrict__ b3) {
    extern __shared__ float sm[];
    float* ET  = sm;                    // [64][ETP]  (E^T, then H^T, then [256][64] staging)
    float* sW2 = sm + 64*ETP;
    float* sW3 = sW2 + 4096;
    float* sB2 = sW3 + 4096;
    float* sB3 = sB2 + 64;
    int tid = threadIdx.x;
    int tx = tid & 7, ty = tid >> 3;

    for (int i = tid; i < 4096; i += 256) { sW2[i] = W2[i]; sW3[i] = W3[i]; }
    if (tid < 64) { sB2[tid] = b2[tid]; sB3[tid] = b3[tid]; }

    // ---- build E^T: one thread per edge row ----
    int B0 = blockIdx.x * 256;
    int g  = B0 + tid;                       // global edge id
    int p  = g / KNN;                        // point id
    int b  = p >> 10;
    int j  = g_idx[g];                       // batch-local neighbor id
    const float* pr = g_p1 + (size_t)p * 64;
    const float* qr = g_q1 + ((size_t)(b << 10) + j) * 64;
    __syncthreads();                         // weights loaded AND ET free
#pragma unroll
    for (int c = 0; c < 64; c += 4) {
        float4 pv = *(const float4*)(pr + c);
        float4 qv = *(const float4*)(qr + c);
        ET[(c+0)*ETP + tid] = fmaxf(pv.x + qv.x, 0.0f);
        ET[(c+1)*ETP + tid] = fmaxf(pv.y + qv.y, 0.0f);
        ET[(c+2)*ETP + tid] = fmaxf(pv.z + qv.z, 0.0f);
        ET[(c+3)*ETP + tid] = fmaxf(pv.w + qv.w, 0.0f);
    }
    __syncthreads();

    float acc[8][8];
    // ---- layer 2: H = relu(E @ W2 + b2) ----
#pragma unroll
    for (int i = 0; i < 8; i++)
#pragma unroll
        for (int jj = 0; jj < 8; jj++) acc[i][jj] = 0.0f;
#pragma unroll 4
    for (int k = 0; k < 64; k++) {
        float4 a0 = *(const float4*)(ET + k*ETP + ty*8);
        float4 a1 = *(const float4*)(ET + k*ETP + ty*8 + 4);
        float4 w0 = *(const float4*)(sW2 + k*64 + tx*8);
        float4 w1 = *(const float4*)(sW2 + k*64 + tx*8 + 4);
        float a[8] = {a0.x,a0.y,a0.z,a0.w,a1.x,a1.y,a1.z,a1.w};
        float w[8] = {w0.x,w0.y,w0.z,w0.w,w1.x,w1.y,w1.z,w1.w};
#pragma unroll
        for (int i = 0; i < 8; i++)
#pragma unroll
            for (int jj = 0; jj < 8; jj++) acc[i][jj] = fmaf(a[i], w[jj], acc[i][jj]);
    }
    float bv2[8], bv3[8];
#pragma unroll
    for (int jj = 0; jj < 8; jj++) { bv2[jj] = sB2[tx*8+jj]; bv3[jj] = sB3[tx*8+jj]; }
    __syncthreads();                         // everyone done reading ET
    // store H^T
#pragma unroll
    for (int jj = 0; jj < 8; jj++)
#pragma unroll
        for (int i = 0; i < 8; i++)
            ET[(tx*8+jj)*ETP + ty*8 + i] = fmaxf(acc[i][jj] + bv2[jj], 0.0f);
    __syncthreads();

    // ---- layer 3: out = H @ W3 + b3 ----
#pragma unroll
    for (int i = 0; i < 8; i++)
#pragma unroll
        for (int jj = 0; jj < 8; jj++) acc[i][jj] = 0.0f;
#pragma unroll 4
    for (int k = 0; k < 64; k++) {
        float4 a0 = *(const float4*)(ET + k*ETP + ty*8);
        float4 a1 = *(const float4*)(ET + k*ETP + ty*8 + 4);
        float4 w0 = *(const float4*)(sW3 + k*64 + tx*8);
        float4 w1 = *(const float4*)(sW3 + k*64 + tx*8 + 4);
        float a[8] = {a0.x,a0.y,a0.z,a0.w,a1.x,a1.y,a1.z,a1.w};
        float w[8] = {w0.x,w0.y,w0.z,w0.w,w1.x,w1.y,w1.z,w1.w};
#pragma unroll
        for (int i = 0; i < 8; i++)
#pragma unroll
            for (int jj = 0; jj < 8; jj++) acc[i][jj] = fmaf(a[i], w[jj], acc[i][jj]);
    }
    __syncthreads();                         // done reading ET, reuse as [256][64]
#pragma unroll
    for (int i = 0; i < 8; i++) {
        float4 v0, v1;
        v0.x = acc[i][0] + bv3[0]; v0.y = acc[i][1] + bv3[1];
        v0.z = acc[i][2] + bv3[2]; v0.w = acc[i][3] + bv3[3];
        v1.x = acc[i][4] + bv3[4]; v1.y = acc[i][5] + bv3[5];
        v1.z = acc[i][6] + bv3[6]; v1.w = acc[i][7] + bv3[7];
        *(float4*)(ET + (ty*8+i)*64 + tx*8)     = v0;
        *(float4*)(ET + (ty*8+i)*64 + tx*8 + 4) = v1;
    }
    __syncthreads();

    // ---- per-point max over edges, atomicMax into f1 (0-init folds relu) ----
    int pFirst = B0 / KNN;
    int pLast  = (B0 + 255) / KNN;
    int nseg   = pLast - pFirst + 1;
    int ch = tid & 63;
    for (int s = tid >> 6; s < nseg; s += 4) {
        int pt = pFirst + s;
        int r0 = max(pt * KNN,       B0) - B0;
        int r1 = min(pt * KNN + KNN, B0 + 256) - B0;
        if (r0 >= r1) continue;
        float m = ET[r0*64 + ch];
        for (int r = r0 + 1; r < r1; r++) m = fmaxf(m, ET[r*64 + ch]);
        atomicMax((int*)&g_f1[(size_t)pt*64 + ch], __float_as_int(m));
    }
}

// ---------------- 5) pairwise distances on 64-d features (tiled GEMM) ------
#define TS 132
__global__ void dist64_kernel() {
    __shared__ float sAt[32 * TS];
    __shared__ float sBt[32 * TS];
    int b  = blockIdx.z;
    int m0 = blockIdx.y * 128, n0 = blockIdx.x * 128;
    int tid = threadIdx.x;
    int tx = tid & 15, ty = tid >> 4;
    const float* F = g_f1 + (size_t)b * NP * 64;

    float acc[8][8], na[8], nb[8];
#pragma unroll
    for (int i = 0; i < 8; i++) {
        na[i] = 0.0f; nb[i] = 0.0f;
#pragma unroll
        for (int j = 0; j < 8; j++) acc[i][j] = 0.0f;
    }
    for (int kc = 0; kc < 2; kc++) {
        __syncthreads();
#pragma unroll
        for (int l = 0; l < 16; l++) {
            int idx = l * 256 + tid;
            int r = idx >> 5, c = idx & 31;
            sAt[c * TS + r] = F[(size_t)(m0 + r) * 64 + kc * 32 + c];
            sBt[c * TS + r] = F[(size_t)(n0 + r) * 64 + kc * 32 + c];
        }
        __syncthreads();
        for (int k = 0; k < 32; k++) {
            float4 a0 = *(const float4*)(sAt + k * TS + ty * 8);
            float4 a1 = *(const float4*)(sAt + k * TS + ty * 8 + 4);
            float4 c0 = *(const float4*)(sBt + k * TS + tx * 8);
            float4 c1 = *(const float4*)(sBt + k * TS + tx * 8 + 4);
            float a[8]  = {a0.x, a0.y, a0.z, a0.w, a1.x, a1.y, a1.z, a1.w};
            float bv[8] = {c0.x, c0.y, c0.z, c0.w, c1.x, c1.y, c1.z, c1.w};
#pragma unroll
            for (int i = 0; i < 8; i++) na[i] = fmaf(a[i], a[i], na[i]);
#pragma unroll
            for (int j = 0; j < 8; j++) nb[j] = fmaf(bv[j], bv[j], nb[j]);
#pragma unroll
            for (int i = 0; i < 8; i++)
#pragma unroll
                for (int j = 0; j < 8; j++) acc[i][j] = fmaf(a[i], bv[j], acc[i][j]);
        }
    }
    float* Dp = g_D + (size_t)b * NP * NP;
#pragma unroll
    for (int i = 0; i < 8; i++) {
        int row = m0 + ty * 8 + i;
#pragma unroll
        for (int j = 0; j < 8; j++) {
            int col = n0 + tx * 8 + j;
            float d = na[i] + nb[j] - 2.0f * acc[i][j];
            Dp[(size_t)row * NP + col] = (row == col) ? CUDART_INF_F : d;
        }
    }
}

// ---------------- 6) EdgeConv2 layer split precompute -----------------------
#define PRE2_SMEM ((8192 + 8192 + 4096) * 4)
__global__ void pre2_kernel(const float* __restrict__ W4,
                            const float* __restrict__ b4) {
    extern __shared__ float sm[];
    float* sWd = sm;              // W4a - W4b  [64][128]
    float* sWb = sm + 8192;       // W4b        [64][128]
    float* sF  = sm + 16384;      // f1 tile    [64][64]
    int tid = threadIdx.x;
    int base = blockIdx.x * 64;
    for (int i = tid; i < 8192; i += 256) {
        int c = i >> 7, t = i & 127;
        float wa = W4[c * 128 + t];
        float wb = W4[(64 + c) * 128 + t];
        sWd[i] = wa - wb;
        sWb[i] = wb;
    }
    for (int i = tid; i < 4096; i += 256) sF[i] = g_f1[(size_t)base * 64 + i];
    __syncthreads();

    int t = tid & 127;
    int half = tid >> 7;
    float bias = b4[t];
    for (int pp = 0; pp < 32; pp++) {
        int lp = (pp << 1) + half;
        const float* fr = sF + lp * 64;
        float accp = bias, accq = 0.0f;
#pragma unroll 8
        for (int c = 0; c < 64; c++) {
            float f = fr[c];
            accp = fmaf(f, sWd[c * 128 + t], accp);
            accq = fmaf(f, sWb[c * 128 + t], accq);
        }
        g_p2[(size_t)(base + lp) * 128 + t] = accp;
        g_q2[(size_t)(base + lp) * 128 + t] = accq;
    }
}

// ---------------- 7) EdgeConv2: max_k relu(p + q) ---------------------------
__global__ void ec2_kernel() {
    int n = blockIdx.x, t = threadIdx.x;
    int b = n >> 10;
    float p = g_p2[(size_t)n * 128 + t];
    const int* idxp = g_idx + n * KNN;
    float best = 0.0f;
#pragma unroll
    for (int k = 0; k < KNN; k++) {
        int j = idxp[k];
        float q = g_q2[((size_t)(b << 10) + j) * 128 + t];
        best = fmaxf(best, p + q);
    }
    g_f2[(size_t)n * 128 + t] = best;
}

// ---------------- 8) pool: relu(f2@Wp+bp), max over points -----------------
__global__ void zero_pool_kernel() {
    int i = blockIdx.x * blockDim.x + threadIdx.x;
    if (i < BB * 512) g_pool[i] = 0.0f;
}

__global__ void pool_kernel(const float* __restrict__ Wp,
                            const float* __restrict__ bp) {
    __shared__ float sAt[32 * TS];
    __shared__ float sBt[32 * TS];
    __shared__ float sred[16 * 128];
    int m0 = blockIdx.x * 128, n0 = blockIdx.y * 128;
    int b  = m0 >> 10;
    int tid = threadIdx.x;
    int tx = tid & 15, ty = tid >> 4;

    float acc[8][8];
#pragma unroll
    for (int i = 0; i < 8; i++)
#pragma unroll
        for (int j = 0; j < 8; j++) acc[i][j] = 0.0f;

    for (int kc = 0; kc < 4; kc++) {
        __syncthreads();
#pragma unroll
        for (int l = 0; l < 16; l++) {
            int idx = l * 256 + tid;
            int r = idx >> 5, c = idx & 31;
            sAt[c * TS + r] = g_f2[(size_t)(m0 + r) * 128 + kc * 32 + c];
        }
#pragma unroll
        for (int l = 0; l < 16; l++) {
            int idx = l * 256 + tid;
            int nl = idx & 127, kk = idx >> 7;
            sBt[kk * TS + nl] = Wp[(size_t)(kc * 32 + kk) * 512 + n0 + nl];
        }
        __syncthreads();
        for (int k = 0; k < 32; k++) {
            float4 a0 = *(const float4*)(sAt + k * TS + ty * 8);
            float4 a1 = *(const float4*)(sAt + k * TS + ty * 8 + 4);
            float4 c0 = *(const float4*)(sBt + k * TS + tx * 8);
            float4 c1 = *(const float4*)(sBt + k * TS + tx * 8 + 4);
            float a[8]  = {a0.x, a0.y, a0.z, a0.w, a1.x, a1.y, a1.z, a1.w};
            float bv[8] = {c0.x, c0.y, c0.z, c0.w, c1.x, c1.y, c1.z, c1.w};
#pragma unroll
            for (int i = 0; i < 8; i++)
#pragma unroll
                for (int j = 0; j < 8; j++) acc[i][j] = fmaf(a[i], bv[j], acc[i][j]);
        }
    }
#pragma unroll
    for (int j = 0; j < 8; j++) {
        int col = n0 + tx * 8 + j;
        float bpv = bp[col];
        float cm = 0.0f;
#pragma unroll
        for (int i = 0; i < 8; i++) cm = fmaxf(cm, acc[i][j] + bpv);
        sred[ty * 128 + tx * 8 + j] = cm;
    }
    __syncthreads();
    if (ty == 0) {
#pragma unroll
        for (int j = 0; j < 8; j++) {
            float cm = 0.0f;
#pragma unroll
            for (int yy = 0; yy < 16; yy++) cm = fmaxf(cm, sred[yy * 128 + tx * 8 + j]);
            atomicMax((int*)&g_pool[b * 512 + n0 + tx * 8 + j], __float_as_int(cm));
        }
    }
}

// ---------------- 9) classifier head ----------------------------------------
__global__ void head_kernel(const float* __restrict__ Wt1, const float* __restrict__ bt1,
                            const float* __restrict__ Wt2, const float* __restrict__ bt2,
                            float* __restrict__ out) {
    __shared__ float sp[512];
    __shared__ float st[256];
    int b = blockIdx.x, t = threadIdx.x;
    sp[t]       = g_pool[b * 512 + t];
    sp[256 + t] = g_pool[b * 512 + 256 + t];
    __syncthreads();
    float acc = bt1[t];
#pragma unroll 8
    for (int c = 0; c < 512; c++) acc = fmaf(sp[c], Wt1[c * 256 + t], acc);
    st[t] = fmaxf(acc, 0.0f);
    __syncthreads();
    if (t < 40) {
        float a2 = bt2[t];
#pragma unroll 8
        for (int c = 0; c < 256; c++) a2 = fmaf(st[c], Wt2[c * 40 + t], a2);
        out[b * 40 + t] = a2;
    }
}

// ---------------- launch -----------------------------------------------------
extern "C" void kernel_launch(void* const* d_in, const int* in_sizes, int n_in,
                              void* d_out, int out_size) {
    const float* x   = (const float*)d_in[0];
    const float* W1  = (const float*)d_in[2];
    const float* b1  = (const float*)d_in[3];
    const float* W2  = (const float*)d_in[4];
    const float* b2  = (const float*)d_in[5];
    const float* W3  = (const float*)d_in[6];
    const float* b3  = (const float*)d_in[7];
    const float* W4  = (const float*)d_in[8];
    const float* b4  = (const float*)d_in[9];
    const float* Wp  = (const float*)d_in[10];
    const float* bp  = (const float*)d_in[11];
    const float* Wt1 = (const float*)d_in[12];
    const float* bt1 = (const float*)d_in[13];
    const float* Wt2 = (const float*)d_in[14];
    const float* bt2 = (const float*)d_in[15];
    float* out = (float*)d_out;

    cudaFuncSetAttribute(ec1_kernel,  cudaFuncAttributeMaxDynamicSharedMemorySize, EC1_SMEM);
    cudaFuncSetAttribute(pre2_kernel, cudaFuncAttributeMaxDynamicSharedMemorySize, PRE2_SMEM);

    // Stage 1: fused kNN on xyz + EdgeConv1 (GEMM-tiled, 2 layers fused)
    knn3_kernel<<<NPTS / 8, 256>>>(x);
    pre1_kernel<<<(NPTS * 64) / 256, 256>>>(x, W1, b1);
    ec1_kernel<<<NEDGE / 256, 256, EC1_SMEM>>>(W2, b2, W3, b3);

    // Stage 2: kNN on 64-d features + EdgeConv2 (layer-split, GEMM-free edges)
    dist64_kernel<<<dim3(8, 8, BB), 256>>>();
    topk_kernel<<<NPTS / 8, 256>>>();
    pre2_kernel<<<NPTS / 64, 256, PRE2_SMEM>>>(W4, b4);
    ec2_kernel<<<NPTS, 128>>>();

    // Stage 3: point MLP + global max pool + head
    zero_pool_kernel<<<16, 1024>>>();
    pool_kernel<<<dim3(256, 4), 256>>>(Wp, bp);
    head_kernel<<<BB, 256>>>(Wt1, bt1, Wt2, bt2, out);
}